// round 4
// baseline (speedup 1.0000x reference)
#include <cuda_runtime.h>
#include <math.h>
#include <float.h>

#define NTHREADS   256
#define T_REAL     200
#define T_PAD      256
#define TILE_T     128
#define E_DIM      64
#define WT_STRIDE  68          // transposed-weight row stride (mult of 4, bank-spread)
#define MASK_VAL_F (-4294967296.0f)   // jnp.float32(-2**32+1) rounds to -2^32

// packed f32x2 FMA: d(2 floats) += a*b elementwise (single FFMA2 issue slot)
__device__ __forceinline__ void ffma2(unsigned long long& d,
                                      unsigned long long a,
                                      unsigned long long b) {
    asm("fma.rn.f32x2 %0, %1, %2, %0;" : "+l"(d) : "l"(a), "l"(b));
}
__device__ __forceinline__ float2 unpk(unsigned long long v) {
    float2 r; asm("mov.b64 {%0,%1}, %2;" : "=f"(r.x), "=f"(r.y) : "l"(v)); return r;
}

__device__ __forceinline__ float warpRedMax(float v) {
    #pragma unroll
    for (int o = 16; o > 0; o >>= 1) v = fmaxf(v, __shfl_xor_sync(0xffffffffu, v, o));
    return v;
}
__device__ __forceinline__ float warpRedSum(float v) {
    #pragma unroll
    for (int o = 16; o > 0; o >>= 1) v += __shfl_xor_sync(0xffffffffu, v, o);
    return v;
}

// Shared memory (floats) ~91.4 KB -> 2 CTAs/SM:
//   keysS : 128*64 = 8192    keys tile (row-major t, i contiguous -> native i-pairs)
//   h1S   : 128*64 = 8192    layer-1 activations (i contiguous)
//   WqT   : 64*68  = 4352    transposed effective layer-1 weights (i contiguous)
//   W2T   : 32*68  = 2176    transposed W2
//   qS,qWbS: 64+64  W3S,b2S: 32+32
//   wS    : 256     redS: 32
#define SMEM_FLOATS (8192 + 8192 + 4352 + 2176 + 64 + 64 + 32 + 32 + 256 + 32)

extern "C" __global__ void __launch_bounds__(NTHREADS, 2)
asp_kernel(const float* __restrict__ query,
           const float* __restrict__ keys,
           const int*   __restrict__ klw,
           const float* __restrict__ W1,
           const float* __restrict__ b1,
           const float* __restrict__ W2,
           const float* __restrict__ b2,
           const float* __restrict__ W3,
           const float* __restrict__ b3,
           float* __restrict__ out)
{
    extern __shared__ float sm[];
    float* keysS = sm;                           // 8192
    float* h1S   = keysS + TILE_T * E_DIM;       // 8192
    float* WqT   = h1S   + TILE_T * E_DIM;       // 4352
    float* W2T   = WqT   + 64 * WT_STRIDE;       // 2176
    float* qS    = W2T   + 32 * WT_STRIDE;       // 64
    float* qWbS  = qS    + 64;                   // 64
    float* W3S   = qWbS  + 64;                   // 32
    float* b2S   = W3S   + 32;                   // 32
    float* wS    = b2S   + 32;                   // 256
    float* redS  = wS    + T_PAD;                // 32

    const int b   = blockIdx.x;
    const int tid = threadIdx.x;

    const float* qg = query + (size_t)b * E_DIM;
    const float* kg = keys  + (size_t)b * T_REAL * E_DIM;

    // ---- keys_len: detect int64 vs int32 storage ----
    int len;
    {
        const bool is64 = ((klw[1] | klw[3] | klw[5] | klw[7] | klw[9] | klw[11]) == 0);
        len = is64 ? klw[2 * b] : klw[b];
    }
    const float b3v = b3[0];

    // ---- Stage small operands ----
    if (tid < 64)                qS[tid]      = qg[tid];
    else if (tid < 96)           W3S[tid-64]  = W3[tid-64];
    else if (tid < 128)          b2S[tid-96]  = b2[tid-96];
    __syncthreads();

    // ---- Transposed effective layer-1 weights:
    //      WqT[j][i] = (W1b - W1c)[i][j] + q_i * W1d[i][j]   (coalesced global reads)
    for (int idx = tid; idx < 64 * 64; idx += NTHREADS) {
        const int i = idx >> 6, j = idx & 63;
        WqT[j * WT_STRIDE + i] =
            W1[(64 + i) * 64 + j] - W1[(128 + i) * 64 + j] + qS[i] * W1[(192 + i) * 64 + j];
    }
    // ---- Transposed W2: W2T[j][i] = W2[i][j]
    for (int idx = tid; idx < 64 * 32; idx += NTHREADS) {
        const int i = idx >> 5, j = idx & 31;
        W2T[j * WT_STRIDE + i] = W2[i * 32 + j];
    }
    // qWb[j] = b1[j] + sum_i q_i * (W1a + W1c)[i][j]
    if (tid < 64) {
        float s = b1[tid];
        #pragma unroll 8
        for (int i = 0; i < 64; i++)
            s += qS[i] * (W1[i*64 + tid] + W1[(128 + i)*64 + tid]);
        qWbS[tid] = s;
    }
    __syncthreads();

    // ================= Two 128-row tiles over T =================
    #pragma unroll 1
    for (int tile = 0; tile < 2; tile++) {
        const int rowBase = tile * TILE_T;

        // ---- keys tile -> SMEM (zero-pad rows >= 200) ----
        {
            const int realRows  = (tile == 0) ? TILE_T : (T_REAL - TILE_T);  // 128 / 72
            const int realWords = realRows * E_DIM / 4;
            float4* d4 = (float4*)keysS;
            const float4* s4 = (const float4*)(kg + rowBase * E_DIM);
            for (int i = tid; i < realWords; i += NTHREADS) d4[i] = s4[i];
            for (int i = realWords + tid; i < TILE_T * E_DIM / 4; i += NTHREADS)
                d4[i] = make_float4(0.f, 0.f, 0.f, 0.f);
        }
        __syncthreads();

        // ---- Layer 1: h1 = relu(qWb + keysT @ Weff)  [128 x 64, K=64] ----
        // Thread tile 8t x 4j; accumulators packed over i-parity (FFMA2).
        {
            const int jt = tid & 15;
            const int tt = tid >> 4;          // 16 groups x 8 rows
            const int j  = jt * 4;
            const int tb = tt * 8;
            unsigned long long c[8][4];
            #pragma unroll
            for (int r = 0; r < 8; r++)
                #pragma unroll
                for (int x = 0; x < 4; x++) c[r][x] = 0ull;

            const float* wq = &WqT[j * WT_STRIDE];
            #pragma unroll 1
            for (int i = 0; i < 64; i += 4) {
                const ulonglong2 w0 = *(const ulonglong2*)(wq + 0 * WT_STRIDE + i);
                const ulonglong2 w1 = *(const ulonglong2*)(wq + 1 * WT_STRIDE + i);
                const ulonglong2 w2 = *(const ulonglong2*)(wq + 2 * WT_STRIDE + i);
                const ulonglong2 w3 = *(const ulonglong2*)(wq + 3 * WT_STRIDE + i);
                #pragma unroll
                for (int r = 0; r < 8; r++) {
                    const ulonglong2 a = *(const ulonglong2*)&keysS[(tb + r) * E_DIM + i];
                    ffma2(c[r][0], a.x, w0.x); ffma2(c[r][0], a.y, w0.y);
                    ffma2(c[r][1], a.x, w1.x); ffma2(c[r][1], a.y, w1.y);
                    ffma2(c[r][2], a.x, w2.x); ffma2(c[r][2], a.y, w2.y);
                    ffma2(c[r][3], a.x, w3.x); ffma2(c[r][3], a.y, w3.y);
                }
            }
            const float q0 = qWbS[j], q1 = qWbS[j+1], q2 = qWbS[j+2], q3 = qWbS[j+3];
            #pragma unroll
            for (int r = 0; r < 8; r++) {
                const float2 v0 = unpk(c[r][0]);
                const float2 v1 = unpk(c[r][1]);
                const float2 v2 = unpk(c[r][2]);
                const float2 v3 = unpk(c[r][3]);
                float4 o;
                o.x = fmaxf(v0.x + v0.y + q0, 0.f);
                o.y = fmaxf(v1.x + v1.y + q1, 0.f);
                o.z = fmaxf(v2.x + v2.y + q2, 0.f);
                o.w = fmaxf(v3.x + v3.y + q3, 0.f);
                *(float4*)&h1S[(tb + r) * E_DIM + j] = o;
            }
        }
        __syncthreads();

        // ---- Layer 2 + 3 fused: h2 = relu(b2 + h1 @ W2); score = h2.W3 + b3 ----
        {
            const int jt = tid & 7;           // 8 col-groups x 4 cols = 32
            const int tt = tid >> 3;          // 32 groups x 4 rows
            const int j  = jt * 4;
            const int tb = tt * 4;
            unsigned long long c[4][4];
            #pragma unroll
            for (int r = 0; r < 4; r++)
                #pragma unroll
                for (int x = 0; x < 4; x++) c[r][x] = 0ull;

            const float* w2p = &W2T[j * WT_STRIDE];
            #pragma unroll 2
            for (int i = 0; i < 64; i += 4) {
                const ulonglong2 w0 = *(const ulonglong2*)(w2p + 0 * WT_STRIDE + i);
                const ulonglong2 w1 = *(const ulonglong2*)(w2p + 1 * WT_STRIDE + i);
                const ulonglong2 w2 = *(const ulonglong2*)(w2p + 2 * WT_STRIDE + i);
                const ulonglong2 w3 = *(const ulonglong2*)(w2p + 3 * WT_STRIDE + i);
                #pragma unroll
                for (int r = 0; r < 4; r++) {
                    const ulonglong2 a = *(const ulonglong2*)&h1S[(tb + r) * E_DIM + i];
                    ffma2(c[r][0], a.x, w0.x); ffma2(c[r][0], a.y, w0.y);
                    ffma2(c[r][1], a.x, w1.x); ffma2(c[r][1], a.y, w1.y);
                    ffma2(c[r][2], a.x, w2.x); ffma2(c[r][2], a.y, w2.y);
                    ffma2(c[r][3], a.x, w3.x); ffma2(c[r][3], a.y, w3.y);
                }
            }
            const float bb0 = b2S[j], bb1 = b2S[j+1], bb2 = b2S[j+2], bb3 = b2S[j+3];
            const float w30 = W3S[j], w31 = W3S[j+1], w32 = W3S[j+2], w33 = W3S[j+3];
            float sp[4];
            #pragma unroll
            for (int r = 0; r < 4; r++) {
                const float2 v0 = unpk(c[r][0]);
                const float2 v1 = unpk(c[r][1]);
                const float2 v2 = unpk(c[r][2]);
                const float2 v3 = unpk(c[r][3]);
                sp[r] = fmaxf(v0.x + v0.y + bb0, 0.f) * w30
                      + fmaxf(v1.x + v1.y + bb1, 0.f) * w31
                      + fmaxf(v2.x + v2.y + bb2, 0.f) * w32
                      + fmaxf(v3.x + v3.y + bb3, 0.f) * w33;
            }
            #pragma unroll
            for (int o = 1; o < 8; o <<= 1) {
                #pragma unroll
                for (int r = 0; r < 4; r++)
                    sp[r] += __shfl_xor_sync(0xffffffffu, sp[r], o);
            }
            if (jt == 0) {
                #pragma unroll
                for (int r = 0; r < 4; r++)
                    wS[rowBase + tb + r] = sp[r] + b3v;
            }
        }
        __syncthreads();
    }

    // ---- Mask + softmax over wS ----
    float sc;
    if (tid < T_REAL) sc = (tid < len) ? wS[tid] : MASK_VAL_F;
    else              sc = -FLT_MAX;

    float m = warpRedMax(sc);
    if ((tid & 31) == 0) redS[tid >> 5] = m;
    __syncthreads();
    float bm = redS[0];
    #pragma unroll
    for (int w = 1; w < 8; w++) bm = fmaxf(bm, redS[w]);
    __syncthreads();
    const float e = (tid < T_REAL) ? expf(sc - bm) : 0.f;
    float s1 = warpRedSum(e);
    if ((tid & 31) == 0) redS[tid >> 5] = s1;
    __syncthreads();
    float bs = 0.f;
    #pragma unroll
    for (int w = 0; w < 8; w++) bs += redS[w];
    wS[tid] = e * (1.0f / bs);
    __syncthreads();

    // ---- Weighted sum: out[e] = sum_t w_t * keys[t][e]  (keys from L2) ----
    {
        const int e_ = tid & 63;
        const int g  = tid >> 6;
        float acc = 0.f;
        for (int t = g; t < T_REAL; t += 4)
            acc += wS[t] * kg[t * E_DIM + e_];
        h1S[g * 64 + e_] = acc;
    }
    __syncthreads();
    if (tid < 64)
        out[(size_t)b * E_DIM + tid] =
            h1S[tid] + h1S[64 + tid] + h1S[128 + tid] + h1S[192 + tid];
}

extern "C" void kernel_launch(void* const* d_in, const int* in_sizes, int n_in,
                              void* d_out, int out_size) {
    const float* query = (const float*)d_in[0];
    const float* keys  = (const float*)d_in[1];
    const int*   klen  = (const int*)  d_in[2];
    const float* W1    = (const float*)d_in[3];
    const float* b1    = (const float*)d_in[4];
    const float* W2    = (const float*)d_in[5];
    const float* b2    = (const float*)d_in[6];
    const float* W3    = (const float*)d_in[7];
    const float* b3    = (const float*)d_in[8];
    float* out = (float*)d_out;

    const int B = in_sizes[0] / E_DIM;
    const size_t smem_bytes = (size_t)SMEM_FLOATS * sizeof(float);

    cudaFuncSetAttribute(asp_kernel,
                         cudaFuncAttributeMaxDynamicSharedMemorySize,
                         (int)smem_bytes);

    asp_kernel<<<B, NTHREADS, smem_bytes>>>(query, keys, klen,
                                            W1, b1, W2, b2, W3, b3, out);
}

// round 6
// speedup vs baseline: 2.2794x; 2.2794x over previous
#include <cuda_runtime.h>
#include <cuda_bf16.h>
#include <stdint.h>
#include <math.h>
#include <float.h>

#define NTHREADS   256
#define T_REAL     200
#define T_PAD      256
#define MASK_VAL_F (-4294967296.0f)   // jnp.float32(-2**32+1) rounds to -2^32

// bf16 SMEM tiles, row stride 72 elements (144 B: 16B-aligned, conflict-free ldmatrix)
#define KST        72
#define ROWB       144

// ---- SMEM byte offsets ----
#define OFF_KH    0                        // keys hi  [256][72] bf16 : 36864
#define OFF_KL    36864                    // keys lo
#define OFF_WQH   73728                    // Weff^T hi [64][72]      :  9216
#define OFF_WQL   82944
#define OFF_W2H   92160                    // W2^T  hi [32][72]       :  4608
#define OFF_W2L   96768
#define OFF_SC    101376                   // fp32 scalars: qS64 qWb64 b2 32 W3 32 wS256 red32
#define SMEM_TOTAL (101376 + 1920)

// ---------------- PTX helpers (baseline sm_80-era only) ----------------
static __device__ __forceinline__ uint32_t smem_u32(const void* p) {
    uint32_t a;
    asm("{ .reg .u64 t; cvta.to.shared.u64 t, %1; cvt.u32.u64 %0, t; }" : "=r"(a) : "l"(p));
    return a;
}

#define LDMX4(r, addr) \
    asm volatile("ldmatrix.sync.aligned.m8n8.x4.shared.b16 {%0,%1,%2,%3}, [%4];" \
        : "=r"((r)[0]), "=r"((r)[1]), "=r"((r)[2]), "=r"((r)[3]) : "r"(addr))
#define LDMX2(r, addr) \
    asm volatile("ldmatrix.sync.aligned.m8n8.x2.shared.b16 {%0,%1}, [%2];" \
        : "=r"((r)[0]), "=r"((r)[1]) : "r"(addr))

#define MMA16816(d, a, b) \
    asm volatile("mma.sync.aligned.m16n8k16.row.col.f32.bf16.bf16.f32 " \
        "{%0,%1,%2,%3},{%4,%5,%6,%7},{%8,%9},{%0,%1,%2,%3};" \
        : "+f"((d)[0]), "+f"((d)[1]), "+f"((d)[2]), "+f"((d)[3]) \
        : "r"((a)[0]), "r"((a)[1]), "r"((a)[2]), "r"((a)[3]), \
          "r"((b)[0]), "r"((b)[1]))

static __device__ __forceinline__ uint32_t bfbits(__nv_bfloat16 h) {
    return (uint32_t)*(unsigned short*)&h;
}
// pack (x0,x1) -> bf16x2 (x0 low), return residuals
static __device__ __forceinline__ uint32_t pack_hi(float x0, float x1, float& r0, float& r1) {
    __nv_bfloat16 h0 = __float2bfloat16(x0), h1 = __float2bfloat16(x1);
    r0 = x0 - __bfloat162float(h0);
    r1 = x1 - __bfloat162float(h1);
    return bfbits(h0) | (bfbits(h1) << 16);
}
static __device__ __forceinline__ uint32_t pack2(float x0, float x1) {
    return bfbits(__float2bfloat16(x0)) | (bfbits(__float2bfloat16(x1)) << 16);
}

__device__ __forceinline__ float warpRedMax(float v) {
    #pragma unroll
    for (int o = 16; o > 0; o >>= 1) v = fmaxf(v, __shfl_xor_sync(0xffffffffu, v, o));
    return v;
}
__device__ __forceinline__ float warpRedSum(float v) {
    #pragma unroll
    for (int o = 16; o > 0; o >>= 1) v += __shfl_xor_sync(0xffffffffu, v, o);
    return v;
}

extern "C" __global__ void __launch_bounds__(NTHREADS, 2)
asp_kernel(const float* __restrict__ query,
           const float* __restrict__ keys,
           const int*   __restrict__ klw,
           const float* __restrict__ W1,
           const float* __restrict__ b1,
           const float* __restrict__ W2,
           const float* __restrict__ b2,
           const float* __restrict__ W3,
           const float* __restrict__ b3,
           float* __restrict__ out)
{
    extern __shared__ char sbase[];
    const uint32_t sb = smem_u32(sbase);

    float* qS   = (float*)(sbase + OFF_SC);          // 64
    float* qWbS = qS   + 64;                         // 64
    float* b2S  = qWbS + 64;                         // 32
    float* W3S  = b2S  + 32;                         // 32
    float* wS   = W3S  + 32;                         // 256
    float* redS = wS   + 256;                        // 32

    const int b    = blockIdx.x;
    const int tid  = threadIdx.x;
    const int lane = tid & 31;
    const int warp = tid >> 5;

    const float* qg = query + (size_t)b * 64;
    const float* kg = keys  + (size_t)b * T_REAL * 64;

    int len;
    {
        const bool is64 = ((klw[1] | klw[3] | klw[5] | klw[7] | klw[9] | klw[11]) == 0);
        len = is64 ? klw[2 * b] : klw[b];
    }
    const float b3v = b3[0];

    // ---- stage small operands ----
    if (tid < 64)       qS[tid]     = qg[tid];
    else if (tid < 96)  W3S[tid-64] = W3[tid-64];
    else if (tid < 128) b2S[tid-96] = b2[tid-96];
    __syncthreads();

    // ---- Weff^T split: WqT[j][i] = W1b[i][j]-W1c[i][j]+q_i*W1d[i][j] ----
    for (int idx = tid; idx < 64 * 64; idx += NTHREADS) {
        const int i = idx >> 6, j = idx & 63;
        const float w = W1[(64+i)*64 + j] - W1[(128+i)*64 + j] + qS[i] * W1[(192+i)*64 + j];
        __nv_bfloat16 h = __float2bfloat16(w);
        *(unsigned short*)(sbase + OFF_WQH + j*ROWB + i*2) = *(unsigned short*)&h;
        __nv_bfloat16 l = __float2bfloat16(w - __bfloat162float(h));
        *(unsigned short*)(sbase + OFF_WQL + j*ROWB + i*2) = *(unsigned short*)&l;
    }
    // ---- W2^T split: W2T[n][i] = W2[i][n] ----
    for (int idx = tid; idx < 64 * 32; idx += NTHREADS) {
        const int i = idx >> 5, n = idx & 31;
        const float w = W2[i * 32 + n];
        __nv_bfloat16 h = __float2bfloat16(w);
        *(unsigned short*)(sbase + OFF_W2H + n*ROWB + i*2) = *(unsigned short*)&h;
        __nv_bfloat16 l = __float2bfloat16(w - __bfloat162float(h));
        *(unsigned short*)(sbase + OFF_W2L + n*ROWB + i*2) = *(unsigned short*)&l;
    }
    // qWb[j] = b1[j] + sum_i q_i * (W1a + W1c)[i][j]
    if (tid < 64) {
        float s = b1[tid];
        #pragma unroll 8
        for (int i = 0; i < 64; i++)
            s += qS[i] * (W1[i*64 + tid] + W1[(128+i)*64 + tid]);
        qWbS[tid] = s;
    }
    // ---- keys split (zero-pad t >= 200) ----
    for (int idx = tid; idx < 256 * 16; idx += NTHREADS) {
        const int row = idx >> 4, q4 = idx & 15;
        float4 v = make_float4(0.f, 0.f, 0.f, 0.f);
        if (row < T_REAL) v = ((const float4*)kg)[row * 16 + q4];
        float r0, r1, r2, r3;
        const uint32_t h01 = pack_hi(v.x, v.y, r0, r1);
        const uint32_t h23 = pack_hi(v.z, v.w, r2, r3);
        *(uint2*)(sbase + OFF_KH + row*ROWB + q4*8) = make_uint2(h01, h23);
        *(uint2*)(sbase + OFF_KL + row*ROWB + q4*8) = make_uint2(pack2(r0, r1), pack2(r2, r3));
    }
    __syncthreads();

    // ============== per-warp register-resident pipeline ==============
    // ldmatrix lane addressing
    const uint32_t laneR16 = lane & 15;            // A-frag row within 16
    const uint32_t laneC   = (lane >> 4) << 3;     // A-frag col half (0/8)
    const uint32_t laneR8  = lane & 7;             // B-frag row within 8
    const uint32_t laneK   = ((lane >> 3) & 1) << 3; // B-frag k half (0/8)

    #pragma unroll 1
    for (int slab = 0; slab < 2; slab++) {
        const int rbase = warp * 32 + slab * 16;

        // ---- layer 1: C1[16 x 64] ----
        float c1[8][4];
        #pragma unroll
        for (int nt = 0; nt < 8; nt++)
            #pragma unroll
            for (int x = 0; x < 4; x++) c1[nt][x] = 0.f;

        #pragma unroll
        for (int kk = 0; kk < 4; kk++) {
            const uint32_t aoff = (uint32_t)(rbase + laneR16) * ROWB + (kk*16 + laneC) * 2;
            uint32_t aH[4], aL[4];
            LDMX4(aH, sb + OFF_KH + aoff);
            LDMX4(aL, sb + OFF_KL + aoff);
            #pragma unroll
            for (int nt = 0; nt < 8; nt++) {
                const uint32_t boff = (uint32_t)(nt*8 + laneR8) * ROWB + (kk*16 + laneK) * 2;
                uint32_t bH[2], bL[2];
                LDMX2(bH, sb + OFF_WQH + boff);
                LDMX2(bL, sb + OFF_WQL + boff);
                MMA16816(c1[nt], aH, bH);
                MMA16816(c1[nt], aH, bL);
                MMA16816(c1[nt], aL, bH);
            }
        }

        // ---- epilogue 1 in regs: h1 = relu(C1 + qWb), split -> layer-2 A frags ----
        uint32_t a2h[4][4], a2l[4][4];
        #pragma unroll
        for (int nt = 0; nt < 8; nt++) {
            const int n0 = nt*8 + 2*(lane & 3);
            const float x0 = fmaxf(c1[nt][0] + qWbS[n0],   0.f);
            const float x1 = fmaxf(c1[nt][1] + qWbS[n0+1], 0.f);
            const float x2 = fmaxf(c1[nt][2] + qWbS[n0],   0.f);
            const float x3 = fmaxf(c1[nt][3] + qWbS[n0+1], 0.f);
            float r0, r1, r2, r3;
            const int kk2 = nt >> 1, s = (nt & 1) * 2;
            a2h[kk2][s+0] = pack_hi(x0, x1, r0, r1);
            a2h[kk2][s+1] = pack_hi(x2, x3, r2, r3);
            a2l[kk2][s+0] = pack2(r0, r1);
            a2l[kk2][s+1] = pack2(r2, r3);
        }

        // ---- layer 2: C2[16 x 32] ----
        float c2[4][4];
        #pragma unroll
        for (int nt = 0; nt < 4; nt++)
            #pragma unroll
            for (int x = 0; x < 4; x++) c2[nt][x] = 0.f;

        #pragma unroll
        for (int kk = 0; kk < 4; kk++) {
            #pragma unroll
            for (int nt = 0; nt < 4; nt++) {
                const uint32_t boff = (uint32_t)(nt*8 + laneR8) * ROWB + (kk*16 + laneK) * 2;
                uint32_t bH[2], bL[2];
                LDMX2(bH, sb + OFF_W2H + boff);
                LDMX2(bL, sb + OFF_W2L + boff);
                MMA16816(c2[nt], a2h[kk], bH);
                MMA16816(c2[nt], a2h[kk], bL);
                MMA16816(c2[nt], a2l[kk], bH);
            }
        }

        // ---- epilogue 2: score = relu(C2 + b2) . W3  (quad reduce) ----
        float p0 = 0.f, p1 = 0.f;
        #pragma unroll
        for (int nt = 0; nt < 4; nt++) {
            const int n0 = nt*8 + 2*(lane & 3);
            const float w0 = W3S[n0], w1 = W3S[n0+1];
            const float bb0 = b2S[n0], bb1 = b2S[n0+1];
            p0 += fmaxf(c2[nt][0] + bb0, 0.f) * w0 + fmaxf(c2[nt][1] + bb1, 0.f) * w1;
            p1 += fmaxf(c2[nt][2] + bb0, 0.f) * w0 + fmaxf(c2[nt][3] + bb1, 0.f) * w1;
        }
        p0 += __shfl_xor_sync(0xffffffffu, p0, 1);
        p0 += __shfl_xor_sync(0xffffffffu, p0, 2);
        p1 += __shfl_xor_sync(0xffffffffu, p1, 1);
        p1 += __shfl_xor_sync(0xffffffffu, p1, 2);
        if ((lane & 3) == 0) {
            wS[rbase + (lane >> 2)]     = p0 + b3v;
            wS[rbase + (lane >> 2) + 8] = p1 + b3v;
        }
    }
    __syncthreads();

    // ---- mask + softmax over wS[256] ----
    float sc;
    if (tid < T_REAL) sc = (tid < len) ? wS[tid] : MASK_VAL_F;
    else              sc = -FLT_MAX;

    float m = warpRedMax(sc);
    if ((tid & 31) == 0) redS[tid >> 5] = m;
    __syncthreads();
    float bm = redS[0];
    #pragma unroll
    for (int w = 1; w < 8; w++) bm = fmaxf(bm, redS[w]);
    __syncthreads();
    const float e = (tid < T_REAL) ? expf(sc - bm) : 0.f;
    float s1 = warpRedSum(e);
    if ((tid & 31) == 0) redS[tid >> 5] = s1;
    __syncthreads();
    float bs = 0.f;
    #pragma unroll
    for (int w = 0; w < 8; w++) bs += redS[w];
    wS[tid] = e * (1.0f / bs);
    __syncthreads();

    // ---- weighted sum: out[e] = sum_t w_t * keys[t][e] (fp32 keys via L2) ----
    float* scr = (float*)(sbase + OFF_WQH);   // reuse as fp32 scratch (256 floats)
    {
        const int e_ = tid & 63;
        const int g  = tid >> 6;
        float acc = 0.f;
        for (int t = g; t < T_REAL; t += 4)
            acc += wS[t] * kg[t * 64 + e_];
        scr[g * 64 + e_] = acc;
    }
    __syncthreads();
    if (tid < 64)
        out[(size_t)b * 64 + tid] =
            scr[tid] + scr[64 + tid] + scr[128 + tid] + scr[192 + tid];
}

extern "C" void kernel_launch(void* const* d_in, const int* in_sizes, int n_in,
                              void* d_out, int out_size) {
    const float* query = (const float*)d_in[0];
    const float* keys  = (const float*)d_in[1];
    const int*   klen  = (const int*)  d_in[2];
    const float* W1    = (const float*)d_in[3];
    const float* b1    = (const float*)d_in[4];
    const float* W2    = (const float*)d_in[5];
    const float* b2    = (const float*)d_in[6];
    const float* W3    = (const float*)d_in[7];
    const float* b3    = (const float*)d_in[8];
    float* out = (float*)d_out;

    const int B = in_sizes[0] / 64;

    cudaFuncSetAttribute(asp_kernel,
                         cudaFuncAttributeMaxDynamicSharedMemorySize,
                         SMEM_TOTAL);

    asp_kernel<<<B, NTHREADS, SMEM_TOTAL>>>(query, keys, klen,
                                            W1, b1, W2, b2, W3, b3, out);
}

// round 7
// speedup vs baseline: 4.0842x; 1.7918x over previous
#include <cuda_runtime.h>
#include <cuda_bf16.h>
#include <stdint.h>
#include <math.h>
#include <float.h>

#define NTHREADS   256
#define T_REAL     200
#define MASK_VAL_F (-4294967296.0f)   // jnp.float32(-2**32+1) rounds to -2^32

// bf16 SMEM tiles, row stride 72 elements (144 B: 16B-aligned, conflict-free ldmatrix)
#define ROWB       144

// ---- SMEM byte offsets ----
#define OFF_KH    0                        // keys hi  [128][72] bf16 : 18432 (per-slab)
#define OFF_KL    18432                    // keys lo
#define OFF_WQH   36864                    // Weff^T hi [64][72]      :  9216
#define OFF_WQL   46080
#define OFF_W2H   55296                    // W2^T  hi [32][72]       :  4608
#define OFF_W2L   59904
#define OFF_SC    64512                    // fp32 scalars
#define SMEM_TOTAL (64512 + 1920)          // 66432 B -> 3 CTAs/SM

// ---------------- PTX helpers (baseline, no sm_103a-only features) ----------------
static __device__ __forceinline__ uint32_t smem_u32(const void* p) {
    uint32_t a;
    asm("{ .reg .u64 t; cvta.to.shared.u64 t, %1; cvt.u32.u64 %0, t; }" : "=r"(a) : "l"(p));
    return a;
}

#define LDMX4(r, addr) \
    asm volatile("ldmatrix.sync.aligned.m8n8.x4.shared.b16 {%0,%1,%2,%3}, [%4];" \
        : "=r"((r)[0]), "=r"((r)[1]), "=r"((r)[2]), "=r"((r)[3]) : "r"(addr))
#define LDMX2(r, addr) \
    asm volatile("ldmatrix.sync.aligned.m8n8.x2.shared.b16 {%0,%1}, [%2];" \
        : "=r"((r)[0]), "=r"((r)[1]) : "r"(addr))

#define MMA16816(d, a, b) \
    asm volatile("mma.sync.aligned.m16n8k16.row.col.f32.bf16.bf16.f32 " \
        "{%0,%1,%2,%3},{%4,%5,%6,%7},{%8,%9},{%0,%1,%2,%3};" \
        : "+f"((d)[0]), "+f"((d)[1]), "+f"((d)[2]), "+f"((d)[3]) \
        : "r"((a)[0]), "r"((a)[1]), "r"((a)[2]), "r"((a)[3]), \
          "r"((b)[0]), "r"((b)[1]))

// split (x0 -> low half, x1 -> high half) into hi bf16x2 + residual-lo bf16x2
static __device__ __forceinline__ uint2 split2(float x0, float x1) {
    uint32_t h;
    asm("cvt.rn.bf16x2.f32 %0, %1, %2;" : "=r"(h) : "f"(x1), "f"(x0));
    const float f0 = __uint_as_float(h << 16);
    const float f1 = __uint_as_float(h & 0xffff0000u);
    uint32_t l;
    asm("cvt.rn.bf16x2.f32 %0, %1, %2;" : "=r"(l) : "f"(x1 - f1), "f"(x0 - f0));
    return make_uint2(h, l);
}

__device__ __forceinline__ float warpRedMax(float v) {
    #pragma unroll
    for (int o = 16; o > 0; o >>= 1) v = fmaxf(v, __shfl_xor_sync(0xffffffffu, v, o));
    return v;
}
__device__ __forceinline__ float warpRedSum(float v) {
    #pragma unroll
    for (int o = 16; o > 0; o >>= 1) v += __shfl_xor_sync(0xffffffffu, v, o);
    return v;
}

extern "C" __global__ void __launch_bounds__(NTHREADS, 3)
asp_kernel(const float* __restrict__ query,
           const float* __restrict__ keys,
           const int*   __restrict__ klw,
           const float* __restrict__ W1,
           const float* __restrict__ b1,
           const float* __restrict__ W2,
           const float* __restrict__ b2,
           const float* __restrict__ W3,
           const float* __restrict__ b3,
           float* __restrict__ out)
{
    extern __shared__ char sbase[];
    const uint32_t sb = smem_u32(sbase);

    float* qS   = (float*)(sbase + OFF_SC);          // 64
    float* qWbS = qS   + 64;                         // 64
    float* b2S  = qWbS + 64;                         // 32
    float* W3S  = b2S  + 32;                         // 32
    float* wS   = W3S  + 32;                         // 256 (also qWb-partial scratch)
    float* redS = wS   + 256;                        // 32

    const int b    = blockIdx.x;
    const int tid  = threadIdx.x;
    const int lane = tid & 31;
    const int warp = tid >> 5;

    const float* qg = query + (size_t)b * 64;
    const float* kg = keys  + (size_t)b * T_REAL * 64;

    int len;
    {
        const bool is64 = ((klw[1] | klw[3] | klw[5] | klw[7] | klw[9] | klw[11]) == 0);
        len = is64 ? klw[2 * b] : klw[b];
    }
    const float b3v = b3[0];

    // ---- stage small operands ----
    if (tid < 64)       qS[tid]     = qg[tid];
    else if (tid < 96)  W3S[tid-64] = W3[tid-64];
    else if (tid < 128) b2S[tid-96] = b2[tid-96];
    __syncthreads();

    // ---- qWb partials: thread (g=tid>>6, j=tid&63) sums i in [16g,16g+16) ----
    {
        const int j = tid & 63, g = tid >> 6;
        float s = 0.f;
        #pragma unroll 4
        for (int i = 16 * g; i < 16 * g + 16; i++)
            s += qS[i] * (W1[i*64 + j] + W1[(128+i)*64 + j]);
        wS[tid] = s;
    }
    // ---- Weff^T split (paired over i): WqT[j][i] hi/lo ----
    for (int idx = tid; idx < 2048; idx += NTHREADS) {
        const int j = idx & 63, i0 = (idx >> 6) * 2;
        const float w0 = W1[(64+i0)*64 + j] - W1[(128+i0)*64 + j] + qS[i0]   * W1[(192+i0)*64 + j];
        const float w1 = W1[(65+i0)*64 + j] - W1[(129+i0)*64 + j] + qS[i0+1] * W1[(193+i0)*64 + j];
        const uint2 p = split2(w0, w1);
        *(uint32_t*)(sbase + OFF_WQH + j*ROWB + i0*2) = p.x;
        *(uint32_t*)(sbase + OFF_WQL + j*ROWB + i0*2) = p.y;
    }
    // ---- W2^T split: W2T[n][i] hi/lo ----
    for (int idx = tid; idx < 1024; idx += NTHREADS) {
        const int n = idx & 31, i0 = (idx >> 5) * 2;
        const uint2 p = split2(W2[i0*32 + n], W2[(i0+1)*32 + n]);
        *(uint32_t*)(sbase + OFF_W2H + n*ROWB + i0*2) = p.x;
        *(uint32_t*)(sbase + OFF_W2L + n*ROWB + i0*2) = p.y;
    }
    __syncthreads();
    if (tid < 64)
        qWbS[tid] = b1[tid] + wS[tid] + wS[64+tid] + wS[128+tid] + wS[192+tid];

    // ldmatrix lane addressing
    const uint32_t laneR16 = lane & 15;
    const uint32_t laneC   = (lane >> 4) << 3;
    const uint32_t laneR8  = lane & 7;
    const uint32_t laneK   = ((lane >> 3) & 1) << 3;

    // ================= two 128-row slabs (keys buffer restaged) =================
    #pragma unroll 1
    for (int slab = 0; slab < 2; slab++) {
        __syncthreads();   // slab0: qWbS ready + wS free; slab1: prior reads done

        // ---- stage keys slab hi/lo (zero-pad t >= 200) ----
        for (int idx = tid; idx < 128 * 16; idx += NTHREADS) {
            const int row = idx >> 4, q4 = idx & 15;
            const int t = slab * 128 + row;
            float4 v = make_float4(0.f, 0.f, 0.f, 0.f);
            if (t < T_REAL) v = ((const float4*)kg)[t * 16 + q4];
            const uint2 p01 = split2(v.x, v.y);
            const uint2 p23 = split2(v.z, v.w);
            *(uint2*)(sbase + OFF_KH + row*ROWB + q4*8) = make_uint2(p01.x, p23.x);
            *(uint2*)(sbase + OFF_KL + row*ROWB + q4*8) = make_uint2(p01.y, p23.y);
        }
        __syncthreads();

        // ---- per-warp 16-row tile ----
        const int lrow = warp * 16;

        uint32_t a2h[4][4], a2l[4][4];

        // layer 1 in two nt-halves (keeps c1 live-range at 16 regs)
        #pragma unroll
        for (int hf = 0; hf < 2; hf++) {
            float c1[4][4];
            #pragma unroll
            for (int q = 0; q < 4; q++)
                #pragma unroll
                for (int x = 0; x < 4; x++) c1[q][x] = 0.f;

            #pragma unroll
            for (int kk = 0; kk < 4; kk++) {
                const uint32_t aoff = (uint32_t)(lrow + laneR16) * ROWB + (kk*16 + laneC) * 2;
                uint32_t aH[4], aL[4];
                LDMX4(aH, sb + OFF_KH + aoff);
                LDMX4(aL, sb + OFF_KL + aoff);
                #pragma unroll
                for (int q = 0; q < 4; q++) {
                    const int nt = hf * 4 + q;
                    const uint32_t boff = (uint32_t)(nt*8 + laneR8) * ROWB + (kk*16 + laneK) * 2;
                    uint32_t bH[2], bL[2];
                    LDMX2(bH, sb + OFF_WQH + boff);
                    LDMX2(bL, sb + OFF_WQL + boff);
                    MMA16816(c1[q], aH, bH);
                    MMA16816(c1[q], aH, bL);
                    MMA16816(c1[q], aL, bH);
                }
            }
            // epilogue 1: relu(C1 + qWb) -> split -> layer-2 A frags (in regs)
            #pragma unroll
            for (int q = 0; q < 4; q++) {
                const int nt = hf * 4 + q;
                const int n0 = nt*8 + 2*(lane & 3);
                const float x0 = fmaxf(c1[q][0] + qWbS[n0],   0.f);
                const float x1 = fmaxf(c1[q][1] + qWbS[n0+1], 0.f);
                const float x2 = fmaxf(c1[q][2] + qWbS[n0],   0.f);
                const float x3 = fmaxf(c1[q][3] + qWbS[n0+1], 0.f);
                const uint2 p01 = split2(x0, x1);
                const uint2 p23 = split2(x2, x3);
                const int kk2 = nt >> 1, s = (nt & 1) * 2;
                a2h[kk2][s+0] = p01.x;  a2h[kk2][s+1] = p23.x;
                a2l[kk2][s+0] = p01.y;  a2l[kk2][s+1] = p23.y;
            }
        }

        // ---- layer 2: C2[16 x 32] ----
        float c2[4][4];
        #pragma unroll
        for (int q = 0; q < 4; q++)
            #pragma unroll
            for (int x = 0; x < 4; x++) c2[q][x] = 0.f;

        #pragma unroll
        for (int kk = 0; kk < 4; kk++) {
            #pragma unroll
            for (int nt = 0; nt < 4; nt++) {
                const uint32_t boff = (uint32_t)(nt*8 + laneR8) * ROWB + (kk*16 + laneK) * 2;
                uint32_t bH[2], bL[2];
                LDMX2(bH, sb + OFF_W2H + boff);
                LDMX2(bL, sb + OFF_W2L + boff);
                MMA16816(c2[nt], a2h[kk], bH);
                MMA16816(c2[nt], a2h[kk], bL);
                MMA16816(c2[nt], a2l[kk], bH);
            }
        }

        // ---- epilogue 2: score = relu(C2 + b2) . W3 (quad reduce) ----
        float p0 = 0.f, p1 = 0.f;
        #pragma unroll
        for (int nt = 0; nt < 4; nt++) {
            const int n0 = nt*8 + 2*(lane & 3);
            const float w0 = W3S[n0], w1 = W3S[n0+1];
            const float bb0 = b2S[n0], bb1 = b2S[n0+1];
            p0 += fmaxf(c2[nt][0] + bb0, 0.f) * w0 + fmaxf(c2[nt][1] + bb1, 0.f) * w1;
            p1 += fmaxf(c2[nt][2] + bb0, 0.f) * w0 + fmaxf(c2[nt][3] + bb1, 0.f) * w1;
        }
        p0 += __shfl_xor_sync(0xffffffffu, p0, 1);
        p0 += __shfl_xor_sync(0xffffffffu, p0, 2);
        p1 += __shfl_xor_sync(0xffffffffu, p1, 1);
        p1 += __shfl_xor_sync(0xffffffffu, p1, 2);
        if ((lane & 3) == 0) {
            wS[slab*128 + lrow + (lane >> 2)]     = p0 + b3v;
            wS[slab*128 + lrow + (lane >> 2) + 8] = p1 + b3v;
        }
    }
    __syncthreads();

    // ---- mask + softmax over wS[256] ----
    float sc;
    if (tid < T_REAL) sc = (tid < len) ? wS[tid] : MASK_VAL_F;
    else              sc = -FLT_MAX;

    float m = warpRedMax(sc);
    if ((tid & 31) == 0) redS[tid >> 5] = m;
    __syncthreads();
    float bm = redS[0];
    #pragma unroll
    for (int w = 1; w < 8; w++) bm = fmaxf(bm, redS[w]);
    __syncthreads();
    const float e = (tid < T_REAL) ? expf(sc - bm) : 0.f;
    float s1 = warpRedSum(e);
    if ((tid & 31) == 0) redS[tid >> 5] = s1;
    __syncthreads();
    float bs = 0.f;
    #pragma unroll
    for (int w = 0; w < 8; w++) bs += redS[w];
    wS[tid] = e * (1.0f / bs);
    __syncthreads();

    // ---- weighted sum: out[e] = sum_t w_t * keys[t][e] (fp32 keys via L2) ----
    float* scr = (float*)(sbase + OFF_WQH);   // reuse as fp32 scratch (256 floats)
    {
        const int e_ = tid & 63;
        const int g  = tid >> 6;
        float acc = 0.f;
        for (int t = g; t < T_REAL; t += 4)
            acc += wS[t] * kg[t * 64 + e_];
        scr[g * 64 + e_] = acc;
    }
    __syncthreads();
    if (tid < 64)
        out[(size_t)b * 64 + tid] =
            scr[tid] + scr[64 + tid] + scr[128 + tid] + scr[192 + tid];
}

extern "C" void kernel_launch(void* const* d_in, const int* in_sizes, int n_in,
                              void* d_out, int out_size) {
    const float* query = (const float*)d_in[0];
    const float* keys  = (const float*)d_in[1];
    const int*   klen  = (const int*)  d_in[2];
    const float* W1    = (const float*)d_in[3];
    const float* b1    = (const float*)d_in[4];
    const float* W2    = (const float*)d_in[5];
    const float* b2    = (const float*)d_in[6];
    const float* W3    = (const float*)d_in[7];
    const float* b3    = (const float*)d_in[8];
    float* out = (float*)d_out;

    const int B = in_sizes[0] / 64;

    cudaFuncSetAttribute(asp_kernel,
                         cudaFuncAttributeMaxDynamicSharedMemorySize,
                         SMEM_TOTAL);

    asp_kernel<<<B, NTHREADS, SMEM_TOTAL>>>(query, keys, klen,
                                            W1, b1, W2, b2, W3, b3, out);
}